// round 4
// baseline (speedup 1.0000x reference)
#include <cuda_runtime.h>
#include <cstdint>

// LogicGatedSNN: spikes = (membrane + x · (states > 50)^T + noise) >= threshold
// x: [8192] fp32 binary, states: [8192, 8192] fp32, out: [8192] fp32
//
// DRAM-bound single-pass 256 MiB stream. Warp-per-row: no barriers in the
// mainloop, per-row reduction is 5 shfls. x staged once per CTA into smem and
// shared by 8 warp-rows. states streamed with __ldcs.

#define IN_F   8192
#define OUT_F  8192
#define NTHR   256
#define WARPS  (NTHR / 32)                 // 8 warp-rows per CTA
#define F4_PER_ROW (IN_F / 4)              // 2048 float4 per row
#define CHUNKS 8                           // 8 chunks x (8 float4/lane)

__global__ __launch_bounds__(NTHR) void snn_warprow_kernel(
    const float* __restrict__ x,        // [IN_F]
    const float* __restrict__ states,   // [OUT_F, IN_F]
    const float* __restrict__ mem,      // [OUT_F]
    const float* __restrict__ thr,      // [OUT_F]
    const float* __restrict__ noise,    // [OUT_F]
    float* __restrict__ out)            // [OUT_F]
{
    __shared__ float4 xs4[F4_PER_ROW];     // 32 KiB

    const int tid = threadIdx.x;

    // Stage x into shared memory once per CTA (amortized over 8 rows)
    const float4* __restrict__ x4 = reinterpret_cast<const float4*>(x);
    #pragma unroll
    for (int i = 0; i < F4_PER_ROW / NTHR; ++i)
        xs4[i * NTHR + tid] = x4[i * NTHR + tid];
    __syncthreads();

    const int wid  = tid >> 5;
    const int lane = tid & 31;
    const int row  = blockIdx.x * WARPS + wid;

    const float4* __restrict__ s4 =
        reinterpret_cast<const float4*>(states + (size_t)row * IN_F);

    float sum = 0.0f;

    #pragma unroll 2
    for (int c = 0; c < CHUNKS; ++c) {
        const int base = c * (F4_PER_ROW / CHUNKS) + lane;  // c*256 + lane

        // 8 independent streaming LDG.128 (coalesced 512B/warp each)
        float4 s[8];
        #pragma unroll
        for (int k = 0; k < 8; ++k)
            s[k] = __ldcs(&s4[base + k * 32]);

        #pragma unroll
        for (int k = 0; k < 8; ++k) {
            const float4 xv = xs4[base + k * 32];
            sum += (s[k].x > 50.0f) ? xv.x : 0.0f;
            sum += (s[k].y > 50.0f) ? xv.y : 0.0f;
            sum += (s[k].z > 50.0f) ? xv.z : 0.0f;
            sum += (s[k].w > 50.0f) ? xv.w : 0.0f;
        }
    }

    // Warp-local reduction; no cross-warp sync needed
    #pragma unroll
    for (int off = 16; off > 0; off >>= 1)
        sum += __shfl_xor_sync(0xffffffffu, sum, off);

    if (lane == 0) {
        const float p = mem[row] + sum + noise[row];
        out[row] = (p >= thr[row]) ? 1.0f : 0.0f;
    }
}

extern "C" void kernel_launch(void* const* d_in, const int* in_sizes, int n_in,
                              void* d_out, int out_size) {
    const float* x      = (const float*)d_in[0];  // spike_input [1, 8192]
    const float* states = (const float*)d_in[1];  // synapse_states [8192, 8192]
    const float* mem    = (const float*)d_in[2];  // membrane_potential [8192]
    const float* thr    = (const float*)d_in[3];  // adaptive_threshold [8192]
    const float* noise  = (const float*)d_in[4];  // noise [8192]
    float* out = (float*)d_out;                   // spikes [8192]

    snn_warprow_kernel<<<OUT_F / WARPS, NTHR>>>(x, states, mem, thr, noise, out);
}

// round 5
// speedup vs baseline: 1.2914x; 1.2914x over previous
#include <cuda_runtime.h>
#include <cstdint>

// LogicGatedSNN: spikes = (membrane + x · (states > 50)^T + noise) >= threshold
// x: [8192] fp32 binary, states: [8192, 8192] fp32, out: [8192] fp32
//
// DRAM-bound 256 MiB single-pass stream. R3 structure (CTA-per-row, MLP=8
// float4 states loads) + x packed once into a 1KiB bitmask so the main kernel
// reads 1 LDG.32 of x per thread instead of 32KiB per CTA (removes 256MB of
// parasitic L1/L2 traffic that was contending with the DRAM stream).

#define IN_F   8192
#define OUT_F  8192
#define NTHR   256
#define VEC_PER_THREAD (IN_F / 4 / NTHR)   // 8 float4 per thread

// Packed x: word t holds bits for thread-slot t's 32 columns.
// bit (4*j + c) = x[4*(j*NTHR + t) + c] != 0
__device__ unsigned g_xbits[NTHR];

__global__ __launch_bounds__(NTHR) void pack_x_kernel(const float* __restrict__ x)
{
    const int tid = threadIdx.x;
    const float4* __restrict__ x4 = reinterpret_cast<const float4*>(x);
    unsigned w = 0;
    #pragma unroll
    for (int j = 0; j < VEC_PER_THREAD; ++j) {
        const float4 v = x4[j * NTHR + tid];   // coalesced per j
        unsigned nib = (v.x != 0.0f ? 1u : 0u)
                     | (v.y != 0.0f ? 2u : 0u)
                     | (v.z != 0.0f ? 4u : 0u)
                     | (v.w != 0.0f ? 8u : 0u);
        w |= nib << (4 * j);
    }
    g_xbits[tid] = w;
}

__global__ __launch_bounds__(NTHR) void snn_bits_kernel(
    const float* __restrict__ states,   // [OUT_F, IN_F]
    const float* __restrict__ mem,      // [OUT_F]
    const float* __restrict__ thr,      // [OUT_F]
    const float* __restrict__ noise,    // [OUT_F]
    float* __restrict__ out)            // [OUT_F]
{
    __shared__ int wsum[NTHR / 32];

    const int tid = threadIdx.x;
    const int row = blockIdx.x;

    const float4* __restrict__ s4 =
        reinterpret_cast<const float4*>(states + (size_t)row * IN_F);

    // states row: 8 independent streaming LDG.128 per thread, issued up front
    float4 s[VEC_PER_THREAD];
    #pragma unroll
    for (int j = 0; j < VEC_PER_THREAD; ++j)
        s[j] = __ldcs(&s4[j * NTHR + tid]);

    const unsigned X = g_xbits[tid];     // 1KiB total, L1-hot

    int cnt = 0;
    #pragma unroll
    for (int j = 0; j < VEC_PER_THREAD; ++j) {
        const unsigned nib = X >> (4 * j);
        cnt += (s[j].x > 50.0f) & (int)(nib & 1u);
        cnt += (s[j].y > 50.0f) & (int)((nib >> 1) & 1u);
        cnt += (s[j].z > 50.0f) & (int)((nib >> 2) & 1u);
        cnt += (s[j].w > 50.0f) & (int)((nib >> 3) & 1u);
    }

    // Warp reduce (int)
    #pragma unroll
    for (int off = 16; off > 0; off >>= 1)
        cnt += __shfl_xor_sync(0xffffffffu, cnt, off);

    if ((tid & 31) == 0) wsum[tid >> 5] = cnt;
    __syncthreads();

    if (tid == 0) {
        int c = 0;
        #pragma unroll
        for (int w = 0; w < NTHR / 32; ++w)
            c += wsum[w];
        const float p = mem[row] + (float)c + noise[row];
        out[row] = (p >= thr[row]) ? 1.0f : 0.0f;
    }
}

extern "C" void kernel_launch(void* const* d_in, const int* in_sizes, int n_in,
                              void* d_out, int out_size) {
    const float* x      = (const float*)d_in[0];  // spike_input [1, 8192]
    const float* states = (const float*)d_in[1];  // synapse_states [8192, 8192]
    const float* mem    = (const float*)d_in[2];  // membrane_potential [8192]
    const float* thr    = (const float*)d_in[3];  // adaptive_threshold [8192]
    const float* noise  = (const float*)d_in[4];  // noise [8192]
    float* out = (float*)d_out;                   // spikes [8192]

    pack_x_kernel<<<1, NTHR>>>(x);
    snn_bits_kernel<<<OUT_F, NTHR>>>(states, mem, thr, noise, out);
}